// round 1
// baseline (speedup 1.0000x reference)
#include <cuda_runtime.h>
#include <cstdint>
#include <math.h>

// Problem dims (fixed)
#define B_      2
#define L_      2048
#define D_      2048
#define M_      4096          // B*L
#define H_      16
#define DK      64
#define DV      128
#define NQK     1024          // H*DK
#define CHUNK   64
#define NCHUNK  32            // L / CHUNK
#define SCALE_QK 0.08838834764831845f   // 128^-0.5
#define INV_NORM 0.0625f                 // 1/16
#define LN_EPS   1e-5f

// ---------------- scratch (static device globals; no allocation) -------------
__device__ float g_q   [(size_t)M_ * NQK];   // 16 MB
__device__ float g_k   [(size_t)M_ * NQK];   // 16 MB (pre-scaled)
__device__ float g_gate[(size_t)M_ * NQK];   // 16 MB  log_sigmoid(kg)/16
__device__ float g_kg1 [(size_t)M_ * 16];    // x @ Wkg1^T
__device__ float g_v   [(size_t)M_ * D_];    // 32 MB
__device__ float g_gp  [(size_t)M_ * D_];    // 32 MB  gproj
__device__ float g_y   [(size_t)M_ * D_];    // 32 MB  silu(gproj)*ln(o)
__device__ float g_S   [(size_t)B_ * H_ * NCHUNK * DK * DV]; // 32 MB chunk states

// ---------------- generic NT SGEMM: C[m,n] = alpha * sum_k A[m,k]B[n,k] + bias[n]
__global__ __launch_bounds__(256) void sgemm_nt(
    const float* __restrict__ A, const float* __restrict__ Bw,
    const float* __restrict__ bias, float* __restrict__ C,
    int M, int N, int K, float alpha)
{
    __shared__ float As[16][132];
    __shared__ float Bs[16][132];
    const int tid = threadIdx.x;
    const int tx = tid & 15;
    const int ty = tid >> 4;
    const int m0 = blockIdx.y * 128;
    const int n0 = blockIdx.x * 128;
    const int lr = tid >> 2;          // 0..63
    const int lc = (tid & 3) << 2;    // 0,4,8,12
    const float* Ap = A  + (size_t)(m0 + lr) * K + lc;
    const float* Bp = Bw + (size_t)(n0 + lr) * K + lc;

    float acc[8][8];
#pragma unroll
    for (int i = 0; i < 8; ++i)
#pragma unroll
        for (int j = 0; j < 8; ++j) acc[i][j] = 0.f;

    for (int kt = 0; kt < K; kt += 16) {
        float4 a0 = *(const float4*)(Ap + kt);
        float4 a1 = *(const float4*)(Ap + (size_t)64 * K + kt);
        float4 b0 = *(const float4*)(Bp + kt);
        float4 b1 = *(const float4*)(Bp + (size_t)64 * K + kt);
        As[lc+0][lr]    = a0.x; As[lc+1][lr]    = a0.y; As[lc+2][lr]    = a0.z; As[lc+3][lr]    = a0.w;
        As[lc+0][lr+64] = a1.x; As[lc+1][lr+64] = a1.y; As[lc+2][lr+64] = a1.z; As[lc+3][lr+64] = a1.w;
        Bs[lc+0][lr]    = b0.x; Bs[lc+1][lr]    = b0.y; Bs[lc+2][lr]    = b0.z; Bs[lc+3][lr]    = b0.w;
        Bs[lc+0][lr+64] = b1.x; Bs[lc+1][lr+64] = b1.y; Bs[lc+2][lr+64] = b1.z; Bs[lc+3][lr+64] = b1.w;
        __syncthreads();
#pragma unroll
        for (int kk = 0; kk < 16; ++kk) {
            float4 av0 = *(const float4*)&As[kk][ty*8];
            float4 av1 = *(const float4*)&As[kk][ty*8+4];
            float4 bv0 = *(const float4*)&Bs[kk][tx*8];
            float4 bv1 = *(const float4*)&Bs[kk][tx*8+4];
            float a[8] = {av0.x,av0.y,av0.z,av0.w,av1.x,av1.y,av1.z,av1.w};
            float b[8] = {bv0.x,bv0.y,bv0.z,bv0.w,bv1.x,bv1.y,bv1.z,bv1.w};
#pragma unroll
            for (int i = 0; i < 8; ++i)
#pragma unroll
                for (int j = 0; j < 8; ++j)
                    acc[i][j] = fmaf(a[i], b[j], acc[i][j]);
        }
        __syncthreads();
    }

    float bb[8];
#pragma unroll
    for (int j = 0; j < 8; ++j) bb[j] = bias ? bias[n0 + tx*8 + j] : 0.f;
#pragma unroll
    for (int i = 0; i < 8; ++i) {
        int m = m0 + ty*8 + i;
        float4 o0, o1;
        o0.x = acc[i][0]*alpha + bb[0]; o0.y = acc[i][1]*alpha + bb[1];
        o0.z = acc[i][2]*alpha + bb[2]; o0.w = acc[i][3]*alpha + bb[3];
        o1.x = acc[i][4]*alpha + bb[4]; o1.y = acc[i][5]*alpha + bb[5];
        o1.z = acc[i][6]*alpha + bb[6]; o1.w = acc[i][7]*alpha + bb[7];
        *(float4*)(C + (size_t)m*N + n0 + tx*8)     = o0;
        *(float4*)(C + (size_t)m*N + n0 + tx*8 + 4) = o1;
    }
}

// ---------------- kg1 = x @ Wkg1^T  ([4096,2048] x [16,2048] -> [4096,16]) ----
__global__ __launch_bounds__(256) void kg1_kernel(
    const float* __restrict__ x, const float* __restrict__ Wkg1,
    float* __restrict__ out)
{
    __shared__ float xs[16][68];
    __shared__ float ws[16][68];
    const int tid = threadIdx.x;
    const int tx = tid & 15;        // n (0..15)
    const int ty = tid >> 4;        // m row within tile
    const int m0 = blockIdx.x * 16;
    const int lrow = tid >> 4;      // 0..15
    const int lcol = (tid & 15) * 4;
    float acc = 0.f;
    for (int kt = 0; kt < D_; kt += 64) {
        float4 xv = *(const float4*)(x    + (size_t)(m0 + lrow)*D_ + kt + lcol);
        float4 wv = *(const float4*)(Wkg1 + (size_t)lrow*D_        + kt + lcol);
        *(float4*)&xs[lrow][lcol] = xv;
        *(float4*)&ws[lrow][lcol] = wv;
        __syncthreads();
#pragma unroll
        for (int kk = 0; kk < 64; ++kk)
            acc = fmaf(xs[ty][kk], ws[tx][kk], acc);
        __syncthreads();
    }
    out[(size_t)(m0 + ty)*16 + tx] = acc;
}

// ---------------- gate = log_sigmoid(kg1 @ Wkg2^T + bkg2) / 16 ---------------
__global__ __launch_bounds__(256) void gate_kernel(
    const float* __restrict__ Wkg2, const float* __restrict__ bkg2)
{
    __shared__ float row[16];
    const int tid = threadIdx.x;
    const int m = blockIdx.x;
    if (tid < 16) row[tid] = g_kg1[(size_t)m*16 + tid];
    __syncthreads();
#pragma unroll
    for (int i = 0; i < 4; ++i) {
        int n = i*256 + tid;
        const float4* wp = (const float4*)(Wkg2 + (size_t)n*16);
        float4 w0 = wp[0], w1 = wp[1], w2 = wp[2], w3 = wp[3];
        float acc = bkg2[n];
        acc += row[0]*w0.x + row[1]*w0.y + row[2]*w0.z + row[3]*w0.w;
        acc += row[4]*w1.x + row[5]*w1.y + row[6]*w1.z + row[7]*w1.w;
        acc += row[8]*w2.x + row[9]*w2.y + row[10]*w2.z + row[11]*w2.w;
        acc += row[12]*w3.x + row[13]*w3.y + row[14]*w3.z + row[15]*w3.w;
        float z = acc;
        float ls = (z >= 0.f) ? (-log1pf(expf(-z))) : (z - log1pf(expf(z)));
        g_gate[(size_t)m*NQK + n] = ls * INV_NORM;
    }
}

// ---------------- pass 1: sequential chunk states -----------------------------
// One CTA per (b,h). Stores state BEFORE each chunk c into g_S[(bh*32+c)].
__global__ __launch_bounds__(512) void state_kernel()
{
    extern __shared__ float sm[];
    float (*Gs)[65]  = (float(*)[65]) sm;                       // 64*65
    float (*kb)[68]  = (float(*)[68])(sm + 64*65);              // 64*68
    float (*vs)[132] = (float(*)[132])(sm + 64*65 + 64*68);     // 64*132

    const int bh = blockIdx.x;
    const int b = bh >> 4, h = bh & 15;
    const int tid = threadIdx.x;
    const int ty = tid >> 5;      // 0..15 -> d block of 4
    const int tx = tid & 31;      // 0..31 -> j block of 4
    const int mb = b * L_;

    float S[4][4];
#pragma unroll
    for (int dd = 0; dd < 4; ++dd)
#pragma unroll
        for (int jj = 0; jj < 4; ++jj) S[dd][jj] = 0.f;

    for (int c = 0; c < NCHUNK; ++c) {
        const int m0 = mb + c * CHUNK;
        // store state before chunk
        float* sp = g_S + (size_t)(bh * NCHUNK + c) * (DK * DV);
#pragma unroll
        for (int dd = 0; dd < 4; ++dd) {
            float4 v4 = make_float4(S[dd][0], S[dd][1], S[dd][2], S[dd][3]);
            *(float4*)(sp + (size_t)(ty*4 + dd)*DV + tx*4) = v4;
        }
        // cumsum of gates
        if (tid < 64) {
            float run = 0.f;
            for (int t = 0; t < CHUNK; ++t) {
                run += g_gate[(size_t)(m0 + t)*NQK + h*DK + tid];
                Gs[t][tid] = run;
            }
        }
        __syncthreads();
        // kbar = k * exp(Gend - Gt); v tile
        for (int e = tid; e < CHUNK*DK; e += 512) {
            int t = e >> 6, d = e & 63;
            kb[t][d] = g_k[(size_t)(m0 + t)*NQK + h*DK + d] * expf(Gs[63][d] - Gs[t][d]);
        }
        for (int e = tid; e < CHUNK*DV; e += 512) {
            int t = e >> 7, j = e & 127;
            vs[t][j] = g_v[(size_t)(m0 + t)*D_ + h*DV + j];
        }
        __syncthreads();
        // S = S*exp(Gend) + kbar^T @ V
        float E[4];
#pragma unroll
        for (int dd = 0; dd < 4; ++dd) E[dd] = expf(Gs[63][ty*4 + dd]);
#pragma unroll
        for (int dd = 0; dd < 4; ++dd)
#pragma unroll
            for (int jj = 0; jj < 4; ++jj) S[dd][jj] *= E[dd];
        for (int t = 0; t < CHUNK; ++t) {
            float4 kv = *(const float4*)&kb[t][ty*4];
            float4 vv = *(const float4*)&vs[t][tx*4];
            float ka[4] = {kv.x, kv.y, kv.z, kv.w};
            float va[4] = {vv.x, vv.y, vv.z, vv.w};
#pragma unroll
            for (int dd = 0; dd < 4; ++dd)
#pragma unroll
                for (int jj = 0; jj < 4; ++jj)
                    S[dd][jj] = fmaf(ka[dd], va[jj], S[dd][jj]);
        }
        __syncthreads();
    }
}

// ---------------- pass 2: chunk outputs + LN + SiLU gating --------------------
// grid (chunk=32, bh=32), 256 threads
__global__ __launch_bounds__(256) void output_kernel()
{
    extern __shared__ float sm[];
    float (*qs)[68]  = (float(*)[68]) sm;                              // 64*68
    float (*ks)[68]  = (float(*)[68])(sm + 64*68);                     // 64*68
    float (*GA)[65]  = (float(*)[65])(sm + 2*64*68);                   // 64*65 (G then A)
    float (*vs)[132] = (float(*)[132])(sm + 2*64*68 + 64*65);          // 64*132
    float (*Sp)[132] = (float(*)[132])(sm + 2*64*68 + 64*65 + 64*132); // 64*132

    const int c  = blockIdx.x;
    const int bh = blockIdx.y;
    const int b = bh >> 4, h = bh & 15;
    const int tid = threadIdx.x;
    const int m0 = b * L_ + c * CHUNK;
    const size_t sbase = (size_t)(bh * NCHUNK + c) * (DK * DV);

    // 1. gate cumsum into GA
    if (tid < 64) {
        float run = 0.f;
        for (int t = 0; t < CHUNK; ++t) {
            run += g_gate[(size_t)(m0 + t)*NQK + h*DK + tid];
            GA[t][tid] = run;
        }
    }
    __syncthreads();
    // 2. q~ and k^
    for (int e = tid; e < CHUNK*DK; e += 256) {
        int t = e >> 6, d = e & 63;
        float G = GA[t][d];
        size_t gi = (size_t)(m0 + t)*NQK + h*DK + d;
        qs[t][d] = g_q[gi] * expf(G);
        ks[t][d] = g_k[gi] * expf(-G);
    }
    // 3. v tile and previous state
    for (int e = tid; e < CHUNK*DV; e += 256) {
        int t = e >> 7, j = e & 127;
        vs[t][j] = g_v[(size_t)(m0 + t)*D_ + h*DV + j];
        Sp[t][j] = g_S[sbase + e];
    }
    __syncthreads();
    // 4. A[t][s] = (s<=t) ? q~_t . k^_s : 0   (overwrite GA)
    for (int e = tid; e < CHUNK*CHUNK; e += 256) {
        int t = e >> 6, s = e & 63;
        float acc = 0.f;
        if (s <= t) {
            const float4* qp = (const float4*)&qs[t][0];
            const float4* kp = (const float4*)&ks[s][0];
#pragma unroll
            for (int d4 = 0; d4 < 16; ++d4) {
                float4 qa = qp[d4], kk4 = kp[d4];
                acc = fmaf(qa.x, kk4.x, acc);
                acc = fmaf(qa.y, kk4.y, acc);
                acc = fmaf(qa.z, kk4.z, acc);
                acc = fmaf(qa.w, kk4.w, acc);
            }
        }
        GA[t][s] = acc;
    }
    __syncthreads();
    // 5. o[t][:] = q~_t @ Sp + A[t,:] @ V ; each thread: one row t, 32 cols
    const int t  = tid >> 2;
    const int qq = tid & 3;
    float o[32];
#pragma unroll
    for (int jj = 0; jj < 32; ++jj) o[jj] = 0.f;

    for (int d = 0; d < DK; ++d) {
        float qv = qs[t][d];
        const float4* sp4 = (const float4*)&Sp[d][qq*32];
#pragma unroll
        for (int j4 = 0; j4 < 8; ++j4) {
            float4 vv = sp4[j4];
            o[j4*4+0] = fmaf(qv, vv.x, o[j4*4+0]);
            o[j4*4+1] = fmaf(qv, vv.y, o[j4*4+1]);
            o[j4*4+2] = fmaf(qv, vv.z, o[j4*4+2]);
            o[j4*4+3] = fmaf(qv, vv.w, o[j4*4+3]);
        }
    }
    for (int s = 0; s <= t; ++s) {
        float av = GA[t][s];
        const float4* vp4 = (const float4*)&vs[s][qq*32];
#pragma unroll
        for (int j4 = 0; j4 < 8; ++j4) {
            float4 vv = vp4[j4];
            o[j4*4+0] = fmaf(av, vv.x, o[j4*4+0]);
            o[j4*4+1] = fmaf(av, vv.y, o[j4*4+1]);
            o[j4*4+2] = fmaf(av, vv.z, o[j4*4+2]);
            o[j4*4+3] = fmaf(av, vv.w, o[j4*4+3]);
        }
    }
    // 6. LayerNorm over the 128-wide row (4 threads per row)
    float s1 = 0.f;
#pragma unroll
    for (int jj = 0; jj < 32; ++jj) s1 += o[jj];
    s1 += __shfl_xor_sync(0xffffffffu, s1, 1);
    s1 += __shfl_xor_sync(0xffffffffu, s1, 2);
    float mean = s1 * (1.f/128.f);
    float s2 = 0.f;
#pragma unroll
    for (int jj = 0; jj < 32; ++jj) { float dv = o[jj] - mean; s2 = fmaf(dv, dv, s2); }
    s2 += __shfl_xor_sync(0xffffffffu, s2, 1);
    s2 += __shfl_xor_sync(0xffffffffu, s2, 2);
    float rstd = rsqrtf(s2 * (1.f/128.f) + LN_EPS);
    // 7. y = silu(gproj) * ln(o)
    const int m = m0 + t;
    const float* gpp = g_gp + (size_t)m*D_ + h*DV + qq*32;
    float*       yp  = g_y  + (size_t)m*D_ + h*DV + qq*32;
#pragma unroll
    for (int jj = 0; jj < 32; ++jj) {
        float gv = gpp[jj];
        float si = gv / (1.f + expf(-gv));
        yp[jj] = si * ((o[jj] - mean) * rstd);
    }
}

// ---------------- host driver -------------------------------------------------
extern "C" void kernel_launch(void* const* d_in, const int* in_sizes, int n_in,
                              void* d_out, int out_size)
{
    const float* x    = (const float*)d_in[0];
    const float* Wq   = (const float*)d_in[1];
    const float* Wk   = (const float*)d_in[2];
    const float* Wkg1 = (const float*)d_in[3];
    const float* Wkg2 = (const float*)d_in[4];
    const float* bkg2 = (const float*)d_in[5];
    const float* Wv   = (const float*)d_in[6];
    const float* Wg   = (const float*)d_in[7];
    const float* bg   = (const float*)d_in[8];
    const float* Wo   = (const float*)d_in[9];
    float* out = (float*)d_out;

    float *pq, *pk, *pv, *pgp, *pkg1, *py;
    cudaGetSymbolAddress((void**)&pq,   g_q);
    cudaGetSymbolAddress((void**)&pk,   g_k);
    cudaGetSymbolAddress((void**)&pv,   g_v);
    cudaGetSymbolAddress((void**)&pgp,  g_gp);
    cudaGetSymbolAddress((void**)&pkg1, g_kg1);
    cudaGetSymbolAddress((void**)&py,   g_y);

    // projections
    sgemm_nt<<<dim3(NQK/128, M_/128), 256>>>(x, Wq, nullptr, pq,  M_, NQK, D_, 1.f);
    sgemm_nt<<<dim3(NQK/128, M_/128), 256>>>(x, Wk, nullptr, pk,  M_, NQK, D_, SCALE_QK);
    sgemm_nt<<<dim3(D_/128,  M_/128), 256>>>(x, Wv, nullptr, pv,  M_, D_,  D_, 1.f);
    sgemm_nt<<<dim3(D_/128,  M_/128), 256>>>(x, Wg, bg,      pgp, M_, D_,  D_, 1.f);
    kg1_kernel<<<M_/16, 256>>>(x, Wkg1, pkg1);
    gate_kernel<<<M_, 256>>>(Wkg2, bkg2);

    // recurrence (chunked)
    const int smem7 = (64*65 + 64*68 + 64*132) * 4;
    const int smem8 = (2*64*68 + 64*65 + 2*64*132) * 4;
    cudaFuncSetAttribute(state_kernel,  cudaFuncAttributeMaxDynamicSharedMemorySize, smem7);
    cudaFuncSetAttribute(output_kernel, cudaFuncAttributeMaxDynamicSharedMemorySize, smem8);
    state_kernel<<<B_*H_, 512, smem7>>>();
    output_kernel<<<dim3(NCHUNK, B_*H_), 256, smem8>>>();

    // out = y @ Wo^T
    sgemm_nt<<<dim3(D_/128, M_/128), 256>>>(py, Wo, nullptr, out, M_, D_, D_, 1.f);
}

// round 3
// speedup vs baseline: 2.0674x; 2.0674x over previous
#include <cuda_runtime.h>
#include <cstdint>
#include <math.h>

// Problem dims (fixed)
#define B_      2
#define L_      2048
#define D_      2048
#define M_      4096          // B*L
#define H_      16
#define DK      64
#define DV      128
#define NQK     1024          // H*DK
#define CHUNK   64
#define NCHUNK  32            // L / CHUNK
#define SCALE_QK 0.08838834764831845f   // 128^-0.5
#define INV_NORM 0.0625f                 // 1/16
#define LN_EPS   1e-5f

// ---------------- scratch (static device globals; no allocation) -------------
__device__ float g_q   [(size_t)M_ * NQK];
__device__ float g_k   [(size_t)M_ * NQK];
__device__ float g_gate[(size_t)M_ * NQK];
__device__ float g_kg1 [(size_t)M_ * 16];
__device__ float g_v   [(size_t)M_ * D_];
__device__ float g_gp  [(size_t)M_ * D_];
__device__ float g_y   [(size_t)M_ * D_];
__device__ float g_S   [(size_t)B_ * H_ * NCHUNK * DK * DV];

// ======================= PTX helpers (non-'a' features only) ==================
__device__ __forceinline__ uint32_t smem_u32(const void* p) {
    uint32_t a;
    asm("{ .reg .u64 t; cvta.to.shared.u64 t, %1; cvt.u32.u64 %0, t; }" : "=r"(a) : "l"(p));
    return a;
}
__device__ __forceinline__ void cp_async16(uint32_t dst, const void* src) {
    asm volatile("cp.async.cg.shared.global [%0], [%1], 16;" :: "r"(dst), "l"(src) : "memory");
}
#define CP_COMMIT() asm volatile("cp.async.commit_group;" ::: "memory")
#define CP_WAIT(N)  asm volatile("cp.async.wait_group %0;" :: "n"(N) : "memory")

__device__ __forceinline__ uint32_t f2tf(float f) {
    uint32_t u;
    asm("cvt.rna.tf32.f32 %0, %1;" : "=r"(u) : "f"(f));
    return u;
}
__device__ __forceinline__ void mma_tf32(float c[4], const uint32_t a[4], const uint32_t b[2]) {
    asm volatile(
        "mma.sync.aligned.m16n8k8.row.col.f32.tf32.tf32.f32 "
        "{%0,%1,%2,%3}, {%4,%5,%6,%7}, {%8,%9}, {%0,%1,%2,%3};"
        : "+f"(c[0]), "+f"(c[1]), "+f"(c[2]), "+f"(c[3])
        : "r"(a[0]), "r"(a[1]), "r"(a[2]), "r"(a[3]), "r"(b[0]), "r"(b[1]));
}

// ======================= tf32 GEMM (mma.sync): C = alpha*A@B^T + bias =========
// A [M,K], Bw [N,K], both row-major fp32. Tile 128x128x32, 8 warps (2x4),
// warp tile 64x32 = 4x4 m16n8 mma tiles. cp.async double-buffered.
#define BM 128
#define BN 128
#define BK 32
#define PITCH 36                         // floats per smem row (pad for banks)
#define TSTRIDE (128*PITCH)              // floats per tile
#define GEMM_SMEM_FL (4*TSTRIDE)         // A[2] + B[2]
#define GEMM_SMEM_BYTES (GEMM_SMEM_FL*4)

__global__ __launch_bounds__(256, 1)
void tf32_gemm(const float* __restrict__ A, const float* __restrict__ Bw,
               const float* __restrict__ bias, float* __restrict__ C,
               int M, int N, int K, float alpha)
{
    extern __shared__ float sm[];
    float* Asm = sm;                 // 2 stages
    float* Bsm = sm + 2*TSTRIDE;     // 2 stages
    const uint32_t Abase_s = smem_u32(Asm);
    const uint32_t Bbase_s = smem_u32(Bsm);

    const int tid = threadIdx.x;
    const int wid = tid >> 5;
    const int lane = tid & 31;
    const int g  = lane >> 2;        // 0..7
    const int t4 = lane & 3;         // 0..3
    const int wm = wid >> 2;         // 0..1 -> 64-row block
    const int wn = wid & 3;          // 0..3 -> 32-col block
    const int m0 = blockIdx.y * BM;
    const int n0 = blockIdx.x * BN;

    const float* Ag = A  + (size_t)m0 * K;
    const float* Bg = Bw + (size_t)n0 * K;
    const int r_ld  = tid >> 3;      // 0..31 base row per thread? no: idx below
    (void)r_ld;

    float cacc[4][4][4];
#pragma unroll
    for (int i = 0; i < 4; ++i)
#pragma unroll
        for (int j = 0; j < 4; ++j)
#pragma unroll
            for (int e = 0; e < 4; ++e) cacc[i][j][e] = 0.f;

    const int niter = K / BK;

    auto load_tile = [&](int kt, int s) {
        const int k0 = kt * BK;
        const uint32_t sa = Abase_s + (uint32_t)s * TSTRIDE * 4;
        const uint32_t sb = Bbase_s + (uint32_t)s * TSTRIDE * 4;
#pragma unroll
        for (int i = 0; i < 4; ++i) {
            int idx = tid + 256*i;          // 0..1023
            int r = idx >> 3, sg = idx & 7;
            cp_async16(sa + (uint32_t)(r*PITCH + sg*4)*4, Ag + (size_t)r*K + k0 + sg*4);
        }
#pragma unroll
        for (int i = 0; i < 4; ++i) {
            int idx = tid + 256*i;
            int r = idx >> 3, sg = idx & 7;
            cp_async16(sb + (uint32_t)(r*PITCH + sg*4)*4, Bg + (size_t)r*K + k0 + sg*4);
        }
    };

    load_tile(0, 0);
    CP_COMMIT();

    for (int kt = 0; kt < niter; ++kt) {
        const int s = kt & 1;
        if (kt + 1 < niter) {
            load_tile(kt + 1, s ^ 1);
            CP_COMMIT();
            CP_WAIT(1);
        } else {
            CP_WAIT(0);
        }
        __syncthreads();

        const float* As = Asm + s * TSTRIDE;
        const float* Bs = Bsm + s * TSTRIDE;
#pragma unroll
        for (int kk = 0; kk < 4; ++kk) {
            uint32_t af[4][4];
#pragma unroll
            for (int mt = 0; mt < 4; ++mt) {
                const int r0 = wm*64 + mt*16 + g;
                const float* pa = As + kk*8 + t4;
                af[mt][0] = f2tf(pa[(r0    )*PITCH    ]);
                af[mt][1] = f2tf(pa[(r0 + 8)*PITCH    ]);
                af[mt][2] = f2tf(pa[(r0    )*PITCH + 4]);
                af[mt][3] = f2tf(pa[(r0 + 8)*PITCH + 4]);
            }
            uint32_t bf[4][2];
#pragma unroll
            for (int nt = 0; nt < 4; ++nt) {
                const int nr = wn*32 + nt*8 + g;
                const float* pb = Bs + (size_t)nr*PITCH + kk*8 + t4;
                bf[nt][0] = f2tf(pb[0]);
                bf[nt][1] = f2tf(pb[4]);
            }
#pragma unroll
            for (int mt = 0; mt < 4; ++mt)
#pragma unroll
                for (int nt = 0; nt < 4; ++nt)
                    mma_tf32(cacc[mt][nt], af[mt], bf[nt]);
        }
        __syncthreads();
    }

    // epilogue
#pragma unroll
    for (int mt = 0; mt < 4; ++mt) {
#pragma unroll
        for (int nt = 0; nt < 4; ++nt) {
            const int col = n0 + wn*32 + nt*8 + 2*t4;
            float b0 = bias ? __ldg(bias + col)     : 0.f;
            float b1 = bias ? __ldg(bias + col + 1) : 0.f;
            const int r0 = m0 + wm*64 + mt*16 + g;
            float2 v0 = make_float2(cacc[mt][nt][0]*alpha + b0, cacc[mt][nt][1]*alpha + b1);
            float2 v1 = make_float2(cacc[mt][nt][2]*alpha + b0, cacc[mt][nt][3]*alpha + b1);
            *(float2*)(C + (size_t)r0      * N + col) = v0;
            *(float2*)(C + (size_t)(r0+8)  * N + col) = v1;
        }
    }
}

// ---------------- kg1 = x @ Wkg1^T  ------------------------------------------
__global__ __launch_bounds__(256) void kg1_kernel(
    const float* __restrict__ x, const float* __restrict__ Wkg1,
    float* __restrict__ out)
{
    __shared__ float xs[16][68];
    __shared__ float ws[16][68];
    const int tid = threadIdx.x;
    const int tx = tid & 15;
    const int ty = tid >> 4;
    const int m0 = blockIdx.x * 16;
    const int lrow = tid >> 4;
    const int lcol = (tid & 15) * 4;
    float acc = 0.f;
    for (int kt = 0; kt < D_; kt += 64) {
        float4 xv = *(const float4*)(x    + (size_t)(m0 + lrow)*D_ + kt + lcol);
        float4 wv = *(const float4*)(Wkg1 + (size_t)lrow*D_        + kt + lcol);
        *(float4*)&xs[lrow][lcol] = xv;
        *(float4*)&ws[lrow][lcol] = wv;
        __syncthreads();
#pragma unroll
        for (int kk = 0; kk < 64; ++kk)
            acc = fmaf(xs[ty][kk], ws[tx][kk], acc);
        __syncthreads();
    }
    out[(size_t)(m0 + ty)*16 + tx] = acc;
}

// ---------------- gate = log_sigmoid(kg1 @ Wkg2^T + bkg2) / 16 ---------------
__global__ __launch_bounds__(256) void gate_kernel(
    const float* __restrict__ Wkg2, const float* __restrict__ bkg2)
{
    __shared__ float row[16];
    const int tid = threadIdx.x;
    const int m = blockIdx.x;
    if (tid < 16) row[tid] = g_kg1[(size_t)m*16 + tid];
    __syncthreads();
#pragma unroll
    for (int i = 0; i < 4; ++i) {
        int n = i*256 + tid;
        const float4* wp = (const float4*)(Wkg2 + (size_t)n*16);
        float4 w0 = wp[0], w1 = wp[1], w2 = wp[2], w3 = wp[3];
        float acc = bkg2[n];
        acc += row[0]*w0.x + row[1]*w0.y + row[2]*w0.z + row[3]*w0.w;
        acc += row[4]*w1.x + row[5]*w1.y + row[6]*w1.z + row[7]*w1.w;
        acc += row[8]*w2.x + row[9]*w2.y + row[10]*w2.z + row[11]*w2.w;
        acc += row[12]*w3.x + row[13]*w3.y + row[14]*w3.z + row[15]*w3.w;
        float z = acc;
        float ls = (z >= 0.f) ? (-log1pf(expf(-z))) : (z - log1pf(expf(z)));
        g_gate[(size_t)m*NQK + n] = ls * INV_NORM;
    }
}

// ---------------- pass 1: chunk states, parallel over dv quarters ------------
__global__ __launch_bounds__(128) void state_kernel()
{
    __shared__ float Gs[64][65];
    __shared__ float kb[64][68];
    __shared__ float vs[64][40];
    const int bq = blockIdx.x;         // dv quarter
    const int bh = blockIdx.y;
    const int b = bh >> 4, h = bh & 15;
    const int tid = threadIdx.x;
    const int ty = tid >> 3;           // 0..15 (dk block of 4)
    const int tx = tid & 7;            // 0..7  (dv block of 4 within 32)
    const int mb = b * L_;

    float S[4][4];
#pragma unroll
    for (int dd = 0; dd < 4; ++dd)
#pragma unroll
        for (int jj = 0; jj < 4; ++jj) S[dd][jj] = 0.f;

    for (int c = 0; c < NCHUNK; ++c) {
        const int m0 = mb + c * CHUNK;
        float* sp = g_S + (size_t)(bh * NCHUNK + c) * (DK * DV) + (size_t)bq * 32;
#pragma unroll
        for (int dd = 0; dd < 4; ++dd)
            *(float4*)(sp + (size_t)(ty*4 + dd)*DV + tx*4) =
                make_float4(S[dd][0], S[dd][1], S[dd][2], S[dd][3]);

        if (tid < 64) {
            float run = 0.f;
            for (int t = 0; t < CHUNK; ++t) {
                run += g_gate[(size_t)(m0 + t)*NQK + h*DK + tid];
                Gs[t][tid] = run;
            }
        }
        __syncthreads();
        for (int e = tid; e < CHUNK*DK; e += 128) {
            int t = e >> 6, d = e & 63;
            kb[t][d] = g_k[(size_t)(m0 + t)*NQK + h*DK + d] * expf(Gs[63][d] - Gs[t][d]);
        }
        for (int e = tid; e < CHUNK*32; e += 128) {
            int t = e >> 5, j = e & 31;
            vs[t][j] = g_v[(size_t)(m0 + t)*D_ + h*DV + bq*32 + j];
        }
        __syncthreads();
        float E[4];
#pragma unroll
        for (int dd = 0; dd < 4; ++dd) E[dd] = expf(Gs[63][ty*4 + dd]);
#pragma unroll
        for (int dd = 0; dd < 4; ++dd)
#pragma unroll
            for (int jj = 0; jj < 4; ++jj) S[dd][jj] *= E[dd];
        for (int t = 0; t < CHUNK; ++t) {
            float4 kv = *(const float4*)&kb[t][ty*4];
            float4 vv = *(const float4*)&vs[t][tx*4];
            float ka[4] = {kv.x, kv.y, kv.z, kv.w};
            float va[4] = {vv.x, vv.y, vv.z, vv.w};
#pragma unroll
            for (int dd = 0; dd < 4; ++dd)
#pragma unroll
                for (int jj = 0; jj < 4; ++jj)
                    S[dd][jj] = fmaf(ka[dd], va[jj], S[dd][jj]);
        }
        __syncthreads();
    }
}

// ---------------- pass 2: chunk outputs + LN + SiLU gating --------------------
__global__ __launch_bounds__(256) void output_kernel()
{
    extern __shared__ float sm[];
    float (*qs)[68]  = (float(*)[68]) sm;
    float (*ks)[68]  = (float(*)[68])(sm + 64*68);
    float (*GA)[65]  = (float(*)[65])(sm + 2*64*68);
    float (*vs)[132] = (float(*)[132])(sm + 2*64*68 + 64*65);
    float (*Sp)[132] = (float(*)[132])(sm + 2*64*68 + 64*65 + 64*132);

    const int c  = blockIdx.x;
    const int bh = blockIdx.y;
    const int b = bh >> 4, h = bh & 15;
    const int tid = threadIdx.x;
    const int m0 = b * L_ + c * CHUNK;
    const size_t sbase = (size_t)(bh * NCHUNK + c) * (DK * DV);

    if (tid < 64) {
        float run = 0.f;
        for (int t = 0; t < CHUNK; ++t) {
            run += g_gate[(size_t)(m0 + t)*NQK + h*DK + tid];
            GA[t][tid] = run;
        }
    }
    __syncthreads();
    for (int e = tid; e < CHUNK*DK; e += 256) {
        int t = e >> 6, d = e & 63;
        float G = GA[t][d];
        size_t gi = (size_t)(m0 + t)*NQK + h*DK + d;
        qs[t][d] = g_q[gi] * expf(G);
        ks[t][d] = g_k[gi] * expf(-G);
    }
    for (int e = tid; e < CHUNK*DV; e += 256) {
        int t = e >> 7, j = e & 127;
        vs[t][j] = g_v[(size_t)(m0 + t)*D_ + h*DV + j];
        Sp[t][j] = g_S[sbase + e];
    }
    __syncthreads();
    for (int e = tid; e < CHUNK*CHUNK; e += 256) {
        int t = e >> 6, s = e & 63;
        float acc = 0.f;
        if (s <= t) {
            const float4* qp = (const float4*)&qs[t][0];
            const float4* kp = (const float4*)&ks[s][0];
#pragma unroll
            for (int d4 = 0; d4 < 16; ++d4) {
                float4 qa = qp[d4], kk4 = kp[d4];
                acc = fmaf(qa.x, kk4.x, acc);
                acc = fmaf(qa.y, kk4.y, acc);
                acc = fmaf(qa.z, kk4.z, acc);
                acc = fmaf(qa.w, kk4.w, acc);
            }
        }
        GA[t][s] = acc;
    }
    __syncthreads();
    const int t  = tid >> 2;
    const int qq = tid & 3;
    float o[32];
#pragma unroll
    for (int jj = 0; jj < 32; ++jj) o[jj] = 0.f;

    for (int d = 0; d < DK; ++d) {
        float qv = qs[t][d];
        const float4* sp4 = (const float4*)&Sp[d][qq*32];
#pragma unroll
        for (int j4 = 0; j4 < 8; ++j4) {
            float4 vv = sp4[j4];
            o[j4*4+0] = fmaf(qv, vv.x, o[j4*4+0]);
            o[j4*4+1] = fmaf(qv, vv.y, o[j4*4+1]);
            o[j4*4+2] = fmaf(qv, vv.z, o[j4*4+2]);
            o[j4*4+3] = fmaf(qv, vv.w, o[j4*4+3]);
        }
    }
    for (int s = 0; s <= t; ++s) {
        float av = GA[t][s];
        const float4* vp4 = (const float4*)&vs[s][qq*32];
#pragma unroll
        for (int j4 = 0; j4 < 8; ++j4) {
            float4 vv = vp4[j4];
            o[j4*4+0] = fmaf(av, vv.x, o[j4*4+0]);
            o[j4*4+1] = fmaf(av, vv.y, o[j4*4+1]);
            o[j4*4+2] = fmaf(av, vv.z, o[j4*4+2]);
            o[j4*4+3] = fmaf(av, vv.w, o[j4*4+3]);
        }
    }
    float s1 = 0.f;
#pragma unroll
    for (int jj = 0; jj < 32; ++jj) s1 += o[jj];
    s1 += __shfl_xor_sync(0xffffffffu, s1, 1);
    s1 += __shfl_xor_sync(0xffffffffu, s1, 2);
    float mean = s1 * (1.f/128.f);
    float s2 = 0.f;
#pragma unroll
    for (int jj = 0; jj < 32; ++jj) { float dv = o[jj] - mean; s2 = fmaf(dv, dv, s2); }
    s2 += __shfl_xor_sync(0xffffffffu, s2, 1);
    s2 += __shfl_xor_sync(0xffffffffu, s2, 2);
    float rstd = rsqrtf(s2 * (1.f/128.f) + LN_EPS);
    const int m = m0 + t;
    const float* gpp = g_gp + (size_t)m*D_ + h*DV + qq*32;
    float*       yp  = g_y  + (size_t)m*D_ + h*DV + qq*32;
#pragma unroll
    for (int jj = 0; jj < 32; ++jj) {
        float gv = gpp[jj];
        float si = gv / (1.f + expf(-gv));
        yp[jj] = si * ((o[jj] - mean) * rstd);
    }
}

// ---------------- host driver -------------------------------------------------
extern "C" void kernel_launch(void* const* d_in, const int* in_sizes, int n_in,
                              void* d_out, int out_size)
{
    const float* x    = (const float*)d_in[0];
    const float* Wq   = (const float*)d_in[1];
    const float* Wk   = (const float*)d_in[2];
    const float* Wkg1 = (const float*)d_in[3];
    const float* Wkg2 = (const float*)d_in[4];
    const float* bkg2 = (const float*)d_in[5];
    const float* Wv   = (const float*)d_in[6];
    const float* Wg   = (const float*)d_in[7];
    const float* bg   = (const float*)d_in[8];
    const float* Wo   = (const float*)d_in[9];
    float* out = (float*)d_out;

    float *pq, *pk, *pv, *pgp, *pkg1, *py;
    cudaGetSymbolAddress((void**)&pq,   g_q);
    cudaGetSymbolAddress((void**)&pk,   g_k);
    cudaGetSymbolAddress((void**)&pv,   g_v);
    cudaGetSymbolAddress((void**)&pgp,  g_gp);
    cudaGetSymbolAddress((void**)&pkg1, g_kg1);
    cudaGetSymbolAddress((void**)&py,   g_y);

    cudaFuncSetAttribute(tf32_gemm, cudaFuncAttributeMaxDynamicSharedMemorySize, GEMM_SMEM_BYTES);

    // projections (tf32 mma.sync tensor-core GEMMs)
    tf32_gemm<<<dim3(NQK/BN, M_/BM), 256, GEMM_SMEM_BYTES>>>(x, Wq, nullptr, pq,  M_, NQK, D_, 1.f);
    tf32_gemm<<<dim3(NQK/BN, M_/BM), 256, GEMM_SMEM_BYTES>>>(x, Wk, nullptr, pk,  M_, NQK, D_, SCALE_QK);
    tf32_gemm<<<dim3(D_/BN,  M_/BM), 256, GEMM_SMEM_BYTES>>>(x, Wv, nullptr, pv,  M_, D_,  D_, 1.f);
    tf32_gemm<<<dim3(D_/BN,  M_/BM), 256, GEMM_SMEM_BYTES>>>(x, Wg, bg,      pgp, M_, D_,  D_, 1.f);
    kg1_kernel<<<M_/16, 256>>>(x, Wkg1, pkg1);
    gate_kernel<<<M_, 256>>>(Wkg2, bkg2);

    // recurrence (chunked)
    const int smem8 = (2*64*68 + 64*65 + 2*64*132) * 4;
    cudaFuncSetAttribute(output_kernel, cudaFuncAttributeMaxDynamicSharedMemorySize, smem8);
    state_kernel<<<dim3(4, B_*H_), 128>>>();
    output_kernel<<<dim3(NCHUNK, B_*H_), 256, smem8>>>();

    // out = y @ Wo^T
    tf32_gemm<<<dim3(D_/BN, M_/BM), 256, GEMM_SMEM_BYTES>>>(py, Wo, nullptr, out, M_, D_, D_, 1.f);
}